// round 7
// baseline (speedup 1.0000x reference)
#include <cuda_runtime.h>
#include <math.h>
#include <stdint.h>

#define N_NODES 6144
#define D_IN    256
#define HID     64
#define OUT_DIM 32
#define ATT_H   128

// ---------------- scratch (device globals; no allocation allowed) ----------
__device__ float g_h0[N_NODES * HID];      // tf32-rounded
__device__ float g_h1[N_NODES * HID];      // tf32-rounded
__device__ float g_ict[N_NODES * HID];     // tf32-rounded itemcls
__device__ float g_part[10 * N_NODES * HID];
__device__ float g_z3[3 * N_NODES * HID];
__device__ float g_z2[2 * N_NODES * HID];
__device__ float g_zii[2 * N_NODES * HID];
__device__ float g_relagg [N_NODES * HID];
__device__ float g_itemcls[N_NODES * HID];
__device__ float g_itemitem[N_NODES * HID];

// ---------------- tf32 / mma / cp.async helpers ------------------------------
__device__ __forceinline__ uint32_t f2tf32(uint32_t bits) {
    uint32_t u;
    asm("cvt.rna.tf32.f32 %0, %1;" : "=r"(u) : "f"(__uint_as_float(bits)));
    return u;
}
__device__ __forceinline__ float f2tf32f(float x) {
    uint32_t u;
    asm("cvt.rna.tf32.f32 %0, %1;" : "=r"(u) : "f"(x));
    return __uint_as_float(u);
}

__device__ __forceinline__ void mma_tf32(float* c, const uint32_t* a, const uint32_t* b) {
    asm("mma.sync.aligned.m16n8k8.row.col.f32.tf32.tf32.f32 "
        "{%0,%1,%2,%3}, {%4,%5,%6,%7}, {%8,%9}, {%0,%1,%2,%3};"
        : "+f"(c[0]), "+f"(c[1]), "+f"(c[2]), "+f"(c[3])
        : "r"(a[0]), "r"(a[1]), "r"(a[2]), "r"(a[3]),
          "r"(b[0]), "r"(b[1]));
}

__device__ __forceinline__ void cp16(float* dst, const float* src) {
    uint32_t d = (uint32_t)__cvta_generic_to_shared(dst);
    asm volatile("cp.async.cg.shared.global [%0], [%1], 16;" :: "r"(d), "l"(src));
}
__device__ __forceinline__ void cp_commit() {
    asm volatile("cp.async.commit_group;" ::: "memory");
}
__device__ __forceinline__ void cp_wait2() {
    asm volatile("cp.async.wait_group 2;" ::: "memory");
}

// ---------------- feature mapping: h = rna_tf32(tanh(feat @ W + b)) ----------
__global__ void __launch_bounds__(256) map_kernel(
    const float* __restrict__ feat, const float* __restrict__ W,
    const float* __restrict__ b, float* __restrict__ out)
{
    int row = blockIdx.x * 4 + threadIdx.y;
    int col = threadIdx.x;
    const float* fr = feat + (size_t)row * D_IN;
    float acc = b[col];
#pragma unroll 8
    for (int k = 0; k < D_IN; k++)
        acc = fmaf(fr[k], W[k * HID + col], acc);
    out[(size_t)row * HID + col] = f2tf32f(tanhf(acc));
}

// ---------------- tf32 rounding copy -----------------------------------------
__global__ void __launch_bounds__(256) round_kernel(
    const float* __restrict__ in, float* __restrict__ out)
{
    int i = blockIdx.x * 256 + threadIdx.x;
    uint4 v = ((const uint4*)in)[i];
    v.x = f2tf32(v.x); v.y = f2tf32(v.y);
    v.z = f2tf32(v.z); v.w = f2tf32(v.w);
    ((uint4*)out)[i] = v;
}

// ---------------- big GEMM, tf32 mma, 4-stage cp.async, 1 barrier/tile -------
// BM=128, BN=64, BK=32. 256 threads = 8 warps (4M x 2N), warp tile 32x32.
#define BM 128
#define BK 32
#define AS_STRIDE 36
#define HS_STRIDE 72
#define STAGES 4
#define A_STAGE (BM * AS_STRIDE)
#define H_STAGE (BK * HS_STRIDE)
#define SPMM_SMEM_BYTES (STAGES * (A_STAGE + H_STAGE) * 4)

__device__ __forceinline__ void spmm_load_tile(
    const float* __restrict__ A, const float* __restrict__ H,
    float* as, float* hs, int row0, int k0, int tid)
{
#pragma unroll
    for (int i = 0; i < 4; i++) {
        int idx = tid + i * 256;
        int r   = idx >> 3;
        int c4  = (idx & 7) << 2;
        cp16(as + r * AS_STRIDE + c4, A + (size_t)(row0 + r) * N_NODES + k0 + c4);
    }
#pragma unroll
    for (int i = 0; i < 2; i++) {
        int idx = tid + i * 256;
        int r   = idx >> 4;
        int c4  = (idx & 15) << 2;
        cp16(hs + r * HS_STRIDE + c4, H + (size_t)(k0 + r) * HID + c4);
    }
}

__global__ void __launch_bounds__(256, 2) spmm_kernel(
    const float* __restrict__ adjA, int nA, const float* __restrict__ hA,
    const float* __restrict__ adjB, const float* __restrict__ hB,
    float* __restrict__ part, int kPerSplit)
{
    extern __shared__ float smem[];
    float* AsBase = smem;
    float* HsBase = smem + STAGES * A_STAGE;

    int b = blockIdx.y;
    const float* A;
    const float* H;
    if (b < nA) { A = adjA + (size_t)b * N_NODES * N_NODES;        H = hA; }
    else        { A = adjB + (size_t)(b - nA) * N_NODES * N_NODES; H = hB; }

    float* Cb = part + ((size_t)blockIdx.z * gridDim.y + b) * (size_t)(N_NODES * HID);

    int tid  = threadIdx.x;
    int lane = tid & 31;
    int warp = tid >> 5;
    int g = lane >> 2;
    int t = lane & 3;
    int wm = (warp & 3) * 32;
    int wn = (warp >> 2) * 32;
    int row0 = blockIdx.x * BM;
    int kbeg = blockIdx.z * kPerSplit;
    int nt = kPerSplit / BK;

    float acc[2][4][4];
#pragma unroll
    for (int mt = 0; mt < 2; mt++)
#pragma unroll
        for (int ntl = 0; ntl < 4; ntl++)
#pragma unroll
            for (int i = 0; i < 4; i++) acc[mt][ntl][i] = 0.f;

    // prologue: tiles 0..2 into stages 0..2 (3 groups)
#pragma unroll
    for (int p = 0; p < STAGES - 1; p++) {
        spmm_load_tile(A, H, AsBase + p * A_STAGE, HsBase + p * H_STAGE,
                       row0, kbeg + p * BK, tid);
        cp_commit();
    }

    for (int j = 0; j < nt; j++) {
        cp_wait2();            // pending <= 2 -> tile j resident (this thread)
        __syncthreads();       // publish tile j; retire stragglers of tile j-1

        // prefetch tile j+3 into stage (j+3)%4 (== stage of tile j-1, now free)
        if (j + 3 < nt) {
            int st = (j + 3) % STAGES;
            spmm_load_tile(A, H, AsBase + st * A_STAGE, HsBase + st * H_STAGE,
                           row0, kbeg + (j + 3) * BK, tid);
        }
        cp_commit();           // uniform group count (possibly empty)

        const uint32_t* as = (const uint32_t*)(AsBase + (j % STAGES) * A_STAGE);
        const uint32_t* hs = (const uint32_t*)(HsBase + (j % STAGES) * H_STAGE);

#pragma unroll
        for (int ks = 0; ks < 4; ks++) {
            int kk = ks * 8;
            uint32_t bf[4][2];
#pragma unroll
            for (int ntl = 0; ntl < 4; ntl++) {
                int col = wn + ntl * 8 + g;
                bf[ntl][0] = hs[(kk + t)     * HS_STRIDE + col];   // pre-rounded
                bf[ntl][1] = hs[(kk + t + 4) * HS_STRIDE + col];
            }
#pragma unroll
            for (int mt = 0; mt < 2; mt++) {
                int rbase = wm + mt * 16;
                uint32_t af[4];
                af[0] = f2tf32(as[(rbase + g)     * AS_STRIDE + kk + t]);
                af[1] = f2tf32(as[(rbase + g + 8) * AS_STRIDE + kk + t]);
                af[2] = f2tf32(as[(rbase + g)     * AS_STRIDE + kk + t + 4]);
                af[3] = f2tf32(as[(rbase + g + 8) * AS_STRIDE + kk + t + 4]);
#pragma unroll
                for (int ntl = 0; ntl < 4; ntl++)
                    mma_tf32(acc[mt][ntl], af, bf[ntl]);
            }
        }
    }

#pragma unroll
    for (int mt = 0; mt < 2; mt++) {
        int r_lo = row0 + wm + mt * 16 + g;
#pragma unroll
        for (int ntl = 0; ntl < 4; ntl++) {
            int col = wn + ntl * 8 + 2 * t;
            *(float2*)&Cb[(size_t)r_lo * HID + col] =
                make_float2(acc[mt][ntl][0], acc[mt][ntl][1]);
            *(float2*)&Cb[(size_t)(r_lo + 8) * HID + col] =
                make_float2(acc[mt][ntl][2], acc[mt][ntl][3]);
        }
    }
}

// ---------------- fused split-K reduce + transform ---------------------------
__global__ void __launch_bounds__(256) relz_kernel(
    const float* __restrict__ part, int NB, int KS, int batch0,
    const float* __restrict__ W, const float* __restrict__ bias,
    float* __restrict__ Z, int wStride, int bStride)
{
    int batch = batch0 + blockIdx.y;
    const float* Wb = W + (size_t)blockIdx.y * wStride;
    const float* bb = bias + (size_t)blockIdx.y * bStride;
    float* Zb = Z + (size_t)blockIdx.y * N_NODES * HID;

    __shared__ float Ws[HID * HID];
    __shared__ float xs[16][HID];

    int tx = threadIdx.x, ty = threadIdx.y;
    int tid = ty * 64 + tx;
    for (int i = tid; i < HID * HID; i += 256)
        Ws[i] = Wb[i];

    int row0 = blockIdx.x * 16;
    const size_t slab = (size_t)N_NODES * HID;
#pragma unroll
    for (int i = 0; i < 4; i++) {
        int idx = tid + i * 256;
        int r = idx >> 6, c = idx & 63;
        float v = 0.f;
        for (int s = 0; s < KS; s++)
            v += part[(size_t)(s * NB + batch) * slab + (size_t)(row0 + r) * HID + c];
        xs[r][c] = v;
    }
    __syncthreads();

    float acc0 = bb[tx], acc1 = acc0, acc2 = acc0, acc3 = acc0;
    int rb = ty * 4;
#pragma unroll
    for (int k = 0; k < HID; k += 4) {
        float w0 = Ws[(k + 0) * HID + tx];
        float w1 = Ws[(k + 1) * HID + tx];
        float w2 = Ws[(k + 2) * HID + tx];
        float w3 = Ws[(k + 3) * HID + tx];
        float4 x0 = *(const float4*)&xs[rb + 0][k];
        float4 x1 = *(const float4*)&xs[rb + 1][k];
        float4 x2 = *(const float4*)&xs[rb + 2][k];
        float4 x3 = *(const float4*)&xs[rb + 3][k];
        acc0 = fmaf(x0.x, w0, fmaf(x0.y, w1, fmaf(x0.z, w2, fmaf(x0.w, w3, acc0))));
        acc1 = fmaf(x1.x, w0, fmaf(x1.y, w1, fmaf(x1.z, w2, fmaf(x1.w, w3, acc1))));
        acc2 = fmaf(x2.x, w0, fmaf(x2.y, w1, fmaf(x2.z, w2, fmaf(x2.w, w3, acc2))));
        acc3 = fmaf(x3.x, w0, fmaf(x3.y, w1, fmaf(x3.z, w2, fmaf(x3.w, w3, acc3))));
    }
    Zb[(size_t)(row0 + rb + 0) * HID + tx] = tanhf(acc0);
    Zb[(size_t)(row0 + rb + 1) * HID + tx] = tanhf(acc1);
    Zb[(size_t)(row0 + rb + 2) * HID + tx] = tanhf(acc2);
    Zb[(size_t)(row0 + rb + 3) * HID + tx] = tanhf(acc3);
}

// ---------------- attention pooling over K slots ----------------------------
__global__ void __launch_bounds__(128) attn_kernel(
    const float* __restrict__ Z, const float* __restrict__ aW,
    const float* __restrict__ ab, const float* __restrict__ aq,
    float* __restrict__ outp, int K)
{
    int n = blockIdx.x;
    int j = threadIdx.x;
    __shared__ float zs[4 * HID];
    __shared__ float red[ATT_H];
    __shared__ float sc[4];

    for (int k = 0; k < K; k++)
        if (j < HID) zs[k * HID + j] = Z[((size_t)k * N_NODES + n) * HID + j];
    __syncthreads();

    for (int k = 0; k < K; k++) {
        float u = ab[j];
#pragma unroll
        for (int d = 0; d < HID; d++)
            u = fmaf(zs[k * HID + d], aW[d * ATT_H + j], u);
        red[j] = tanhf(u) * aq[j];
        __syncthreads();
#pragma unroll
        for (int off = 64; off >= 1; off >>= 1) {
            if (j < off) red[j] += red[j + off];
            __syncthreads();
        }
        if (j == 0) sc[k] = red[0];
        __syncthreads();
    }

    float mx = -1e30f;
    for (int k = 0; k < K; k++) mx = fmaxf(mx, sc[k]);
    float e[4]; float den = 0.f;
    for (int k = 0; k < K; k++) { e[k] = expf(sc[k] - mx); den += e[k]; }

    if (j < HID) {
        float o = 0.f;
        for (int k = 0; k < K; k++) o += (e[k] / den) * zs[k * HID + j];
        outp[(size_t)n * HID + j] = o;
    }
}

// ---------------- final: attention over {relagg, itemitem}, then project ----
__global__ void __launch_bounds__(128) final_kernel(
    const float* __restrict__ Hrel, const float* __restrict__ Hii,
    const float* __restrict__ aW, const float* __restrict__ ab,
    const float* __restrict__ aq, const float* __restrict__ Wout,
    const float* __restrict__ bout, float* __restrict__ out, int out_total)
{
    int n = blockIdx.x;
    int j = threadIdx.x;
    __shared__ float zs[2 * HID];
    __shared__ float red[ATT_H];
    __shared__ float sc[2];
    __shared__ float pooled[HID];

    if (j < HID) {
        zs[j]       = Hrel[(size_t)n * HID + j];
        zs[HID + j] = Hii [(size_t)n * HID + j];
    }
    __syncthreads();

    for (int k = 0; k < 2; k++) {
        float u = ab[j];
#pragma unroll
        for (int d = 0; d < HID; d++)
            u = fmaf(zs[k * HID + d], aW[d * ATT_H + j], u);
        red[j] = tanhf(u) * aq[j];
        __syncthreads();
#pragma unroll
        for (int off = 64; off >= 1; off >>= 1) {
            if (j < off) red[j] += red[j + off];
            __syncthreads();
        }
        if (j == 0) sc[k] = red[0];
        __syncthreads();
    }

    float mx = fmaxf(sc[0], sc[1]);
    float e0 = expf(sc[0] - mx), e1 = expf(sc[1] - mx);
    float den = e0 + e1;
    float b0 = e0 / den, b1 = e1 / den;

    if (j < HID) pooled[j] = b0 * zs[j] + b1 * zs[HID + j];
    __syncthreads();

    if (j < OUT_DIM) {
        float o = bout[j];
#pragma unroll
        for (int d = 0; d < HID; d++)
            o = fmaf(pooled[d], Wout[d * OUT_DIM + j], o);
        out[(size_t)n * OUT_DIM + j] = o;
    }
    if (out_total > N_NODES * OUT_DIM && j < HID)
        out[(size_t)N_NODES * OUT_DIM + (size_t)n * HID + j] = pooled[j];
}

// ---------------- launch ----------------------------------------------------
extern "C" void kernel_launch(void* const* d_in, const int* in_sizes, int n_in,
                              void* d_out, int out_size)
{
    const float* feat_item = (const float*)d_in[0];
    const float* feat_user = (const float*)d_in[1];
    const float* adj_ii    = (const float*)d_in[2];
    const float* adj_mp    = (const float*)d_in[3];
    const float* adj_ui    = (const float*)d_in[4];
    const float* W_map0 = (const float*)d_in[5];
    const float* b_map0 = (const float*)d_in[6];
    const float* W_map1 = (const float*)d_in[7];
    const float* b_map1 = (const float*)d_in[8];
    const float* W_rel  = (const float*)d_in[9];
    const float* b_rel  = (const float*)d_in[10];
    const float* rel_aW = (const float*)d_in[11];
    const float* rel_ab = (const float*)d_in[12];
    const float* rel_aq = (const float*)d_in[13];
    const float* W_sch  = (const float*)d_in[14];
    const float* b_sch  = (const float*)d_in[15];
    const float* sch_aW = (const float*)d_in[16];
    const float* sch_ab = (const float*)d_in[17];
    const float* sch_aq = (const float*)d_in[18];
    const float* W_ii   = (const float*)d_in[19];
    const float* b_ii   = (const float*)d_in[20];
    const float* ii_aW  = (const float*)d_in[21];
    const float* ii_ab  = (const float*)d_in[22];
    const float* ii_aq  = (const float*)d_in[23];
    const float* fin_aW = (const float*)d_in[24];
    const float* fin_ab = (const float*)d_in[25];
    const float* fin_aq = (const float*)d_in[26];
    const float* W_out  = (const float*)d_in[27];
    const float* b_out  = (const float*)d_in[28];

    float *h0, *h1, *ict, *partb, *z3, *z2, *zii, *relagg, *itemcls, *itemitem;
    cudaGetSymbolAddress((void**)&h0,  g_h0);
    cudaGetSymbolAddress((void**)&h1,  g_h1);
    cudaGetSymbolAddress((void**)&ict, g_ict);
    cudaGetSymbolAddress((void**)&partb, g_part);
    cudaGetSymbolAddress((void**)&z3, g_z3);
    cudaGetSymbolAddress((void**)&z2, g_z2);
    cudaGetSymbolAddress((void**)&zii, g_zii);
    cudaGetSymbolAddress((void**)&relagg,   g_relagg);
    cudaGetSymbolAddress((void**)&itemcls,  g_itemcls);
    cudaGetSymbolAddress((void**)&itemitem, g_itemitem);

    cudaFuncSetAttribute(spmm_kernel,
                         cudaFuncAttributeMaxDynamicSharedMemorySize,
                         SPMM_SMEM_BYTES);

    dim3 blk64x4(64, 4);

    // Stage 1: feature mapping (outputs pre-rounded to tf32)
    map_kernel<<<N_NODES / 4, blk64x4>>>(feat_item, W_map0, b_map0, h0);
    map_kernel<<<N_NODES / 4, blk64x4>>>(feat_user, W_map1, b_map1, h1);

    // Stage 2: phase-A GEMMs (3x adj_mp@h0 + 2x adj_ui@h1), split-K=2
    spmm_kernel<<<dim3(N_NODES / BM, 5, 2), 256, SPMM_SMEM_BYTES>>>(
        adj_mp, 3, h0, adj_ui, h1, partb, N_NODES / 2);

    // Stage 3: fused reduce+transform, then attention pooling
    relz_kernel<<<dim3(N_NODES / 16, 3), blk64x4>>>(
        partb, 5, 2, 0, W_rel, b_rel, z3, HID * HID, HID);
    relz_kernel<<<dim3(N_NODES / 16, 2), blk64x4>>>(
        partb, 5, 2, 3, W_sch, b_sch, z2, 0, 0);
    attn_kernel<<<N_NODES, 128>>>(z3, rel_aW, rel_ab, rel_aq, relagg, 3);
    attn_kernel<<<N_NODES, 128>>>(z2, sch_aW, sch_ab, sch_aq, itemcls, 2);
    round_kernel<<<N_NODES * HID / 1024, 256>>>(itemcls, ict);

    // Stage 4: phase-B GEMMs (2x adj_ii@itemcls), split-K=3
    spmm_kernel<<<dim3(N_NODES / BM, 2, 3), 256, SPMM_SMEM_BYTES>>>(
        adj_ii, 2, ict, adj_ii, ict, partb, N_NODES / 3);

    // Stage 5: fused reduce+transform + attention
    relz_kernel<<<dim3(N_NODES / 16, 2), blk64x4>>>(
        partb, 2, 3, 0, W_ii, b_ii, zii, HID * HID, HID);
    attn_kernel<<<N_NODES, 128>>>(zii, ii_aW, ii_ab, ii_aq, itemitem, 2);

    // Stage 6: final attention + projection
    final_kernel<<<N_NODES, 128>>>(relagg, itemitem, fin_aW, fin_ab, fin_aq,
                                   W_out, b_out, (float*)d_out, out_size);
}

// round 8
// speedup vs baseline: 1.0528x; 1.0528x over previous
#include <cuda_runtime.h>
#include <math.h>
#include <stdint.h>

#define N_NODES 6144
#define D_IN    256
#define HID     64
#define OUT_DIM 32
#define ATT_H   128

#define ADJ_SCALE   2048.0f
#define ADJ_UNSCALE 4.8828125e-4f   // 1/2048

// ---------------- scratch (device globals; no allocation allowed) ----------
__device__ float    g_h0[N_NODES * HID];
__device__ float    g_h1[N_NODES * HID];
__device__ uint32_t g_h0p[N_NODES * HID / 2];   // packed fp16 pairs [k/2][64]
__device__ uint32_t g_h1p[N_NODES * HID / 2];
__device__ uint32_t g_ictp[N_NODES * HID / 2];
__device__ float g_part[10 * N_NODES * HID];
__device__ float g_z3[3 * N_NODES * HID];
__device__ float g_z2[2 * N_NODES * HID];
__device__ float g_zii[2 * N_NODES * HID];
__device__ float g_relagg [N_NODES * HID];
__device__ float g_itemcls[N_NODES * HID];
__device__ float g_itemitem[N_NODES * HID];

// ---------------- helpers -----------------------------------------------------
__device__ __forceinline__ uint32_t pack_f16x2(float lo, float hi) {
    uint32_t r;
    asm("cvt.rn.f16x2.f32 %0, %1, %2;" : "=r"(r) : "f"(hi), "f"(lo));
    return r;
}
// load fp32 pair from smem, scale by ADJ_SCALE, pack to half2
__device__ __forceinline__ uint32_t ld_scale_pack(const float* p) {
    float2 v = *(const float2*)p;
    return pack_f16x2(v.x * ADJ_SCALE, v.y * ADJ_SCALE);
}

__device__ __forceinline__ void mma_fp16(float* c, const uint32_t* a, const uint32_t* b) {
    asm("mma.sync.aligned.m16n8k16.row.col.f32.f16.f16.f32 "
        "{%0,%1,%2,%3}, {%4,%5,%6,%7}, {%8,%9}, {%0,%1,%2,%3};"
        : "+f"(c[0]), "+f"(c[1]), "+f"(c[2]), "+f"(c[3])
        : "r"(a[0]), "r"(a[1]), "r"(a[2]), "r"(a[3]),
          "r"(b[0]), "r"(b[1]));
}

__device__ __forceinline__ void cp16(void* dst, const void* src) {
    uint32_t d = (uint32_t)__cvta_generic_to_shared(dst);
    asm volatile("cp.async.cg.shared.global [%0], [%1], 16;" :: "r"(d), "l"(src));
}
__device__ __forceinline__ void cp_commit() {
    asm volatile("cp.async.commit_group;" ::: "memory");
}
__device__ __forceinline__ void cp_wait2() {
    asm volatile("cp.async.wait_group 2;" ::: "memory");
}

// ---------------- feature mapping: h = tanh(feat @ W + b) -------------------
__global__ void __launch_bounds__(256) map_kernel(
    const float* __restrict__ feat, const float* __restrict__ W,
    const float* __restrict__ b, float* __restrict__ out)
{
    int row = blockIdx.x * 4 + threadIdx.y;
    int col = threadIdx.x;
    const float* fr = feat + (size_t)row * D_IN;
    float acc = b[col];
#pragma unroll 8
    for (int k = 0; k < D_IN; k++)
        acc = fmaf(fr[k], W[k * HID + col], acc);
    out[(size_t)row * HID + col] = tanhf(acc);
}

// ---------------- pack: f32 [N][64] -> u32 half2 [N/2][64] -------------------
__global__ void __launch_bounds__(256) pack_kernel(
    const float* __restrict__ in, uint32_t* __restrict__ out)
{
    int i = blockIdx.x * 256 + threadIdx.x;   // over N/2 * 64
    int r = i >> 6, c = i & 63;
    float lo = in[(size_t)(2 * r) * HID + c];
    float hi = in[(size_t)(2 * r + 1) * HID + c];
    out[i] = pack_f16x2(lo, hi);
}

// ---------------- big GEMM, fp16 m16n8k16, 4-stage cp.async ------------------
// BM=128, BN=64, BK=32. 256 threads = 8 warps (4M x 2N), warp tile 32x32.
#define BM 128
#define BK 32
#define AS_STRIDE 36            // fp32 words per A row
#define HS_STRIDE 72            // u32 words per H' pair-row (16 pair-rows/tile)
#define STAGES 4
#define A_STAGE (BM * AS_STRIDE)
#define H_STAGE (16 * HS_STRIDE)
#define SPMM_SMEM_BYTES (STAGES * (A_STAGE + H_STAGE) * 4)

__device__ __forceinline__ void spmm_load_tile(
    const float* __restrict__ A, const uint32_t* __restrict__ Hp,
    float* as, uint32_t* hs, int row0, int k0, int tid)
{
#pragma unroll
    for (int i = 0; i < 4; i++) {
        int idx = tid + i * 256;
        int r   = idx >> 3;
        int c4  = (idx & 7) << 2;
        cp16(as + r * AS_STRIDE + c4, A + (size_t)(row0 + r) * N_NODES + k0 + c4);
    }
    {
        int r  = tid >> 4;                  // pair-row 0..15
        int c4 = (tid & 15) << 2;           // word chunk
        cp16(hs + r * HS_STRIDE + c4,
             Hp + (size_t)((k0 >> 1) + r) * HID + c4);
    }
}

__global__ void __launch_bounds__(256, 2) spmm_kernel(
    const float* __restrict__ adjA, int nA, const uint32_t* __restrict__ hA,
    const float* __restrict__ adjB, const uint32_t* __restrict__ hB,
    float* __restrict__ part, int kPerSplit)
{
    extern __shared__ float smem[];
    float*    AsBase = smem;
    uint32_t* HsBase = (uint32_t*)(smem + STAGES * A_STAGE);

    int b = blockIdx.y;
    const float* A;
    const uint32_t* Hp;
    if (b < nA) { A = adjA + (size_t)b * N_NODES * N_NODES;        Hp = hA; }
    else        { A = adjB + (size_t)(b - nA) * N_NODES * N_NODES; Hp = hB; }

    float* Cb = part + ((size_t)blockIdx.z * gridDim.y + b) * (size_t)(N_NODES * HID);

    int tid  = threadIdx.x;
    int lane = tid & 31;
    int warp = tid >> 5;
    int g = lane >> 2;
    int t = lane & 3;
    int wm = (warp & 3) * 32;
    int wn = (warp >> 2) * 32;
    int row0 = blockIdx.x * BM;
    int kbeg = blockIdx.z * kPerSplit;
    int nt = kPerSplit / BK;

    float acc[2][4][4];
#pragma unroll
    for (int mt = 0; mt < 2; mt++)
#pragma unroll
        for (int ntl = 0; ntl < 4; ntl++)
#pragma unroll
            for (int i = 0; i < 4; i++) acc[mt][ntl][i] = 0.f;

#pragma unroll
    for (int p = 0; p < STAGES - 1; p++) {
        spmm_load_tile(A, Hp, AsBase + p * A_STAGE, HsBase + p * H_STAGE,
                       row0, kbeg + p * BK, tid);
        cp_commit();
    }

    for (int j = 0; j < nt; j++) {
        cp_wait2();
        __syncthreads();

        if (j + 3 < nt) {
            int st = (j + 3) % STAGES;
            spmm_load_tile(A, Hp, AsBase + st * A_STAGE, HsBase + st * H_STAGE,
                           row0, kbeg + (j + 3) * BK, tid);
        }
        cp_commit();

        const float*    as = AsBase + (j % STAGES) * A_STAGE;
        const uint32_t* hs = HsBase + (j % STAGES) * H_STAGE;

#pragma unroll
        for (int c = 0; c < 2; c++) {          // two k16 chunks per BK=32
            int kk  = c * 16;                  // k offset (halves == fp32 words)
            int kp0 = c * 8;                   // pair-row offset
            uint32_t bf[4][2];
#pragma unroll
            for (int ntl = 0; ntl < 4; ntl++) {
                int col = wn + ntl * 8 + g;
                bf[ntl][0] = hs[(kp0 + t)     * HS_STRIDE + col];
                bf[ntl][1] = hs[(kp0 + t + 4) * HS_STRIDE + col];
            }
#pragma unroll
            for (int mt = 0; mt < 2; mt++) {
                int rbase = wm + mt * 16;
                uint32_t af[4];
                af[0] = ld_scale_pack(&as[(rbase + g)     * AS_STRIDE + kk + 2 * t]);
                af[1] = ld_scale_pack(&as[(rbase + g + 8) * AS_STRIDE + kk + 2 * t]);
                af[2] = ld_scale_pack(&as[(rbase + g)     * AS_STRIDE + kk + 2 * t + 8]);
                af[3] = ld_scale_pack(&as[(rbase + g + 8) * AS_STRIDE + kk + 2 * t + 8]);
#pragma unroll
                for (int ntl = 0; ntl < 4; ntl++)
                    mma_fp16(acc[mt][ntl], af, bf[ntl]);
            }
        }
    }

#pragma unroll
    for (int mt = 0; mt < 2; mt++) {
        int r_lo = row0 + wm + mt * 16 + g;
#pragma unroll
        for (int ntl = 0; ntl < 4; ntl++) {
            int col = wn + ntl * 8 + 2 * t;
            *(float2*)&Cb[(size_t)r_lo * HID + col] =
                make_float2(acc[mt][ntl][0] * ADJ_UNSCALE,
                            acc[mt][ntl][1] * ADJ_UNSCALE);
            *(float2*)&Cb[(size_t)(r_lo + 8) * HID + col] =
                make_float2(acc[mt][ntl][2] * ADJ_UNSCALE,
                            acc[mt][ntl][3] * ADJ_UNSCALE);
        }
    }
}

// ---------------- fused split-K reduce + transform ---------------------------
__global__ void __launch_bounds__(256) relz_kernel(
    const float* __restrict__ part, int NB, int KS, int batch0,
    const float* __restrict__ W, const float* __restrict__ bias,
    float* __restrict__ Z, int wStride, int bStride)
{
    int batch = batch0 + blockIdx.y;
    const float* Wb = W + (size_t)blockIdx.y * wStride;
    const float* bb = bias + (size_t)blockIdx.y * bStride;
    float* Zb = Z + (size_t)blockIdx.y * N_NODES * HID;

    __shared__ float Ws[HID * HID];
    __shared__ float xs[16][HID];

    int tx = threadIdx.x, ty = threadIdx.y;
    int tid = ty * 64 + tx;
    for (int i = tid; i < HID * HID; i += 256)
        Ws[i] = Wb[i];

    int row0 = blockIdx.x * 16;
    const size_t slab = (size_t)N_NODES * HID;
#pragma unroll
    for (int i = 0; i < 4; i++) {
        int idx = tid + i * 256;
        int r = idx >> 6, c = idx & 63;
        float v = 0.f;
        for (int s = 0; s < KS; s++)
            v += part[(size_t)(s * NB + batch) * slab + (size_t)(row0 + r) * HID + c];
        xs[r][c] = v;
    }
    __syncthreads();

    float acc0 = bb[tx], acc1 = acc0, acc2 = acc0, acc3 = acc0;
    int rb = ty * 4;
#pragma unroll
    for (int k = 0; k < HID; k += 4) {
        float w0 = Ws[(k + 0) * HID + tx];
        float w1 = Ws[(k + 1) * HID + tx];
        float w2 = Ws[(k + 2) * HID + tx];
        float w3 = Ws[(k + 3) * HID + tx];
        float4 x0 = *(const float4*)&xs[rb + 0][k];
        float4 x1 = *(const float4*)&xs[rb + 1][k];
        float4 x2 = *(const float4*)&xs[rb + 2][k];
        float4 x3 = *(const float4*)&xs[rb + 3][k];
        acc0 = fmaf(x0.x, w0, fmaf(x0.y, w1, fmaf(x0.z, w2, fmaf(x0.w, w3, acc0))));
        acc1 = fmaf(x1.x, w0, fmaf(x1.y, w1, fmaf(x1.z, w2, fmaf(x1.w, w3, acc1))));
        acc2 = fmaf(x2.x, w0, fmaf(x2.y, w1, fmaf(x2.z, w2, fmaf(x2.w, w3, acc2))));
        acc3 = fmaf(x3.x, w0, fmaf(x3.y, w1, fmaf(x3.z, w2, fmaf(x3.w, w3, acc3))));
    }
    Zb[(size_t)(row0 + rb + 0) * HID + tx] = tanhf(acc0);
    Zb[(size_t)(row0 + rb + 1) * HID + tx] = tanhf(acc1);
    Zb[(size_t)(row0 + rb + 2) * HID + tx] = tanhf(acc2);
    Zb[(size_t)(row0 + rb + 3) * HID + tx] = tanhf(acc3);
}

// ---------------- attention pooling over K slots ----------------------------
__global__ void __launch_bounds__(128) attn_kernel(
    const float* __restrict__ Z, const float* __restrict__ aW,
    const float* __restrict__ ab, const float* __restrict__ aq,
    float* __restrict__ outp, int K)
{
    int n = blockIdx.x;
    int j = threadIdx.x;
    __shared__ float zs[4 * HID];
    __shared__ float red[ATT_H];
    __shared__ float sc[4];

    for (int k = 0; k < K; k++)
        if (j < HID) zs[k * HID + j] = Z[((size_t)k * N_NODES + n) * HID + j];
    __syncthreads();

    for (int k = 0; k < K; k++) {
        float u = ab[j];
#pragma unroll
        for (int d = 0; d < HID; d++)
            u = fmaf(zs[k * HID + d], aW[d * ATT_H + j], u);
        red[j] = tanhf(u) * aq[j];
        __syncthreads();
#pragma unroll
        for (int off = 64; off >= 1; off >>= 1) {
            if (j < off) red[j] += red[j + off];
            __syncthreads();
        }
        if (j == 0) sc[k] = red[0];
        __syncthreads();
    }

    float mx = -1e30f;
    for (int k = 0; k < K; k++) mx = fmaxf(mx, sc[k]);
    float e[4]; float den = 0.f;
    for (int k = 0; k < K; k++) { e[k] = expf(sc[k] - mx); den += e[k]; }

    if (j < HID) {
        float o = 0.f;
        for (int k = 0; k < K; k++) o += (e[k] / den) * zs[k * HID + j];
        outp[(size_t)n * HID + j] = o;
    }
}

// ---------------- final: attention over {relagg, itemitem}, then project ----
__global__ void __launch_bounds__(128) final_kernel(
    const float* __restrict__ Hrel, const float* __restrict__ Hii,
    const float* __restrict__ aW, const float* __restrict__ ab,
    const float* __restrict__ aq, const float* __restrict__ Wout,
    const float* __restrict__ bout, float* __restrict__ out, int out_total)
{
    int n = blockIdx.x;
    int j = threadIdx.x;
    __shared__ float zs[2 * HID];
    __shared__ float red[ATT_H];
    __shared__ float sc[2];
    __shared__ float pooled[HID];

    if (j < HID) {
        zs[j]       = Hrel[(size_t)n * HID + j];
        zs[HID + j] = Hii [(size_t)n * HID + j];
    }
    __syncthreads();

    for (int k = 0; k < 2; k++) {
        float u = ab[j];
#pragma unroll
        for (int d = 0; d < HID; d++)
            u = fmaf(zs[k * HID + d], aW[d * ATT_H + j], u);
        red[j] = tanhf(u) * aq[j];
        __syncthreads();
#pragma unroll
        for (int off = 64; off >= 1; off >>= 1) {
            if (j < off) red[j] += red[j + off];
            __syncthreads();
        }
        if (j == 0) sc[k] = red[0];
        __syncthreads();
    }

    float mx = fmaxf(sc[0], sc[1]);
    float e0 = expf(sc[0] - mx), e1 = expf(sc[1] - mx);
    float den = e0 + e1;
    float b0 = e0 / den, b1 = e1 / den;

    if (j < HID) pooled[j] = b0 * zs[j] + b1 * zs[HID + j];
    __syncthreads();

    if (j < OUT_DIM) {
        float o = bout[j];
#pragma unroll
        for (int d = 0; d < HID; d++)
            o = fmaf(pooled[d], Wout[d * OUT_DIM + j], o);
        out[(size_t)n * OUT_DIM + j] = o;
    }
    if (out_total > N_NODES * OUT_DIM && j < HID)
        out[(size_t)N_NODES * OUT_DIM + (size_t)n * HID + j] = pooled[j];
}

// ---------------- launch ----------------------------------------------------
extern "C" void kernel_launch(void* const* d_in, const int* in_sizes, int n_in,
                              void* d_out, int out_size)
{
    const float* feat_item = (const float*)d_in[0];
    const float* feat_user = (const float*)d_in[1];
    const float* adj_ii    = (const float*)d_in[2];
    const float* adj_mp    = (const float*)d_in[3];
    const float* adj_ui    = (const float*)d_in[4];
    const float* W_map0 = (const float*)d_in[5];
    const float* b_map0 = (const float*)d_in[6];
    const float* W_map1 = (const float*)d_in[7];
    const float* b_map1 = (const float*)d_in[8];
    const float* W_rel  = (const float*)d_in[9];
    const float* b_rel  = (const float*)d_in[10];
    const float* rel_aW = (const float*)d_in[11];
    const float* rel_ab = (const float*)d_in[12];
    const float* rel_aq = (const float*)d_in[13];
    const float* W_sch  = (const float*)d_in[14];
    const float* b_sch  = (const float*)d_in[15];
    const float* sch_aW = (const float*)d_in[16];
    const float* sch_ab = (const float*)d_in[17];
    const float* sch_aq = (const float*)d_in[18];
    const float* W_ii   = (const float*)d_in[19];
    const float* b_ii   = (const float*)d_in[20];
    const float* ii_aW  = (const float*)d_in[21];
    const float* ii_ab  = (const float*)d_in[22];
    const float* ii_aq  = (const float*)d_in[23];
    const float* fin_aW = (const float*)d_in[24];
    const float* fin_ab = (const float*)d_in[25];
    const float* fin_aq = (const float*)d_in[26];
    const float* W_out  = (const float*)d_in[27];
    const float* b_out  = (const float*)d_in[28];

    float *h0, *h1, *partb, *z3, *z2, *zii, *relagg, *itemcls, *itemitem;
    uint32_t *h0p, *h1p, *ictp;
    cudaGetSymbolAddress((void**)&h0,  g_h0);
    cudaGetSymbolAddress((void**)&h1,  g_h1);
    cudaGetSymbolAddress((void**)&h0p, g_h0p);
    cudaGetSymbolAddress((void**)&h1p, g_h1p);
    cudaGetSymbolAddress((void**)&ictp, g_ictp);
    cudaGetSymbolAddress((void**)&partb, g_part);
    cudaGetSymbolAddress((void**)&z3, g_z3);
    cudaGetSymbolAddress((void**)&z2, g_z2);
    cudaGetSymbolAddress((void**)&zii, g_zii);
    cudaGetSymbolAddress((void**)&relagg,   g_relagg);
    cudaGetSymbolAddress((void**)&itemcls,  g_itemcls);
    cudaGetSymbolAddress((void**)&itemitem, g_itemitem);

    cudaFuncSetAttribute(spmm_kernel,
                         cudaFuncAttributeMaxDynamicSharedMemorySize,
                         SPMM_SMEM_BYTES);

    dim3 blk64x4(64, 4);
    const int packBlocks = N_NODES * HID / 2 / 256;

    // Stage 1: feature mapping + fp16 pack
    map_kernel<<<N_NODES / 4, blk64x4>>>(feat_item, W_map0, b_map0, h0);
    map_kernel<<<N_NODES / 4, blk64x4>>>(feat_user, W_map1, b_map1, h1);
    pack_kernel<<<packBlocks, 256>>>(h0, h0p);
    pack_kernel<<<packBlocks, 256>>>(h1, h1p);

    // Stage 2: phase-A GEMMs (3x adj_mp@h0 + 2x adj_ui@h1), split-K=2
    spmm_kernel<<<dim3(N_NODES / BM, 5, 2), 256, SPMM_SMEM_BYTES>>>(
        adj_mp, 3, h0p, adj_ui, h1p, partb, N_NODES / 2);

    // Stage 3: fused reduce+transform, then attention pooling
    relz_kernel<<<dim3(N_NODES / 16, 3), blk64x4>>>(
        partb, 5, 2, 0, W_rel, b_rel, z3, HID * HID, HID);
    relz_kernel<<<dim3(N_NODES / 16, 2), blk64x4>>>(
        partb, 5, 2, 3, W_sch, b_sch, z2, 0, 0);
    attn_kernel<<<N_NODES, 128>>>(z3, rel_aW, rel_ab, rel_aq, relagg, 3);
    attn_kernel<<<N_NODES, 128>>>(z2, sch_aW, sch_ab, sch_aq, itemcls, 2);
    pack_kernel<<<packBlocks, 256>>>(itemcls, ictp);

    // Stage 4: phase-B GEMMs (2x adj_ii@itemcls), split-K=3
    spmm_kernel<<<dim3(N_NODES / BM, 2, 3), 256, SPMM_SMEM_BYTES>>>(
        adj_ii, 2, ictp, adj_ii, ictp, partb, N_NODES / 3);

    // Stage 5: fused reduce+transform + attention
    relz_kernel<<<dim3(N_NODES / 16, 2), blk64x4>>>(
        partb, 2, 3, 0, W_ii, b_ii, zii, HID * HID, HID);
    attn_kernel<<<N_NODES, 128>>>(zii, ii_aW, ii_ab, ii_aq, itemitem, 2);

    // Stage 6: final attention + projection
    final_kernel<<<N_NODES, 128>>>(relagg, itemitem, fin_aW, fin_ab, fin_aq,
                                   W_out, b_out, (float*)d_out, out_size);
}

// round 9
// speedup vs baseline: 1.0731x; 1.0193x over previous
#include <cuda_runtime.h>
#include <math.h>
#include <stdint.h>

#define N_NODES 6144
#define D_IN    256
#define HID     64
#define OUT_DIM 32
#define ATT_H   128

#define ADJ_SCALE   2048.0f
#define ADJ_UNSCALE 4.8828125e-4f   // 1/2048

// ---------------- scratch (device globals; no allocation allowed) ----------
__device__ float    g_h0[N_NODES * HID];
__device__ float    g_h1[N_NODES * HID];
__device__ uint32_t g_h0p[N_NODES * HID / 2];   // packed fp16 pairs [k/2][64]
__device__ uint32_t g_h1p[N_NODES * HID / 2];
__device__ uint32_t g_ictp[N_NODES * HID / 2];
__device__ float g_part[10 * N_NODES * HID];
__device__ float g_z3[3 * N_NODES * HID];
__device__ float g_z2[2 * N_NODES * HID];
__device__ float g_zii[2 * N_NODES * HID];
__device__ float g_relagg [N_NODES * HID];
__device__ float g_itemcls[N_NODES * HID];
__device__ float g_itemitem[N_NODES * HID];

// ---------------- helpers -----------------------------------------------------
__device__ __forceinline__ uint32_t pack_f16x2(float lo, float hi) {
    uint32_t r;
    asm("cvt.rn.f16x2.f32 %0, %1, %2;" : "=r"(r) : "f"(hi), "f"(lo));
    return r;
}
__device__ __forceinline__ uint32_t ld_scale_pack(const float* p) {
    float2 v = *(const float2*)p;
    return pack_f16x2(v.x * ADJ_SCALE, v.y * ADJ_SCALE);
}

__device__ __forceinline__ void mma_fp16(float* c, const uint32_t* a, const uint32_t* b) {
    asm("mma.sync.aligned.m16n8k16.row.col.f32.f16.f16.f32 "
        "{%0,%1,%2,%3}, {%4,%5,%6,%7}, {%8,%9}, {%0,%1,%2,%3};"
        : "+f"(c[0]), "+f"(c[1]), "+f"(c[2]), "+f"(c[3])
        : "r"(a[0]), "r"(a[1]), "r"(a[2]), "r"(a[3]),
          "r"(b[0]), "r"(b[1]));
}

__device__ __forceinline__ void cp16(void* dst, const void* src) {
    uint32_t d = (uint32_t)__cvta_generic_to_shared(dst);
    asm volatile("cp.async.cg.shared.global [%0], [%1], 16;" :: "r"(d), "l"(src));
}
__device__ __forceinline__ void cp_commit() {
    asm volatile("cp.async.commit_group;" ::: "memory");
}
__device__ __forceinline__ void cp_wait1() {
    asm volatile("cp.async.wait_group 1;" ::: "memory");
}

// ---------------- feature mapping: h = tanh(feat @ W + b) -------------------
__global__ void __launch_bounds__(256) map_kernel(
    const float* __restrict__ feat, const float* __restrict__ W,
    const float* __restrict__ b, float* __restrict__ out)
{
    int row = blockIdx.x * 4 + threadIdx.y;
    int col = threadIdx.x;
    const float* fr = feat + (size_t)row * D_IN;
    float acc = b[col];
#pragma unroll 8
    for (int k = 0; k < D_IN; k++)
        acc = fmaf(fr[k], W[k * HID + col], acc);
    out[(size_t)row * HID + col] = tanhf(acc);
}

// ---------------- pack: f32 [N][64] -> u32 half2 [N/2][64] -------------------
__global__ void __launch_bounds__(256) pack_kernel(
    const float* __restrict__ in, uint32_t* __restrict__ out)
{
    int i = blockIdx.x * 256 + threadIdx.x;
    int r = i >> 6, c = i & 63;
    float lo = in[(size_t)(2 * r) * HID + c];
    float hi = in[(size_t)(2 * r + 1) * HID + c];
    out[i] = pack_f16x2(lo, hi);
}

// ---------------- big GEMM, fp16 m16n8k16, 3-stage cp.async, 3 CTA/SM --------
// BM=128, BN=64, BK=32. 256 threads = 8 warps (4M x 2N), warp tile 32x32.
#define BM 128
#define BK 32
#define AS_STRIDE 36            // fp32 words per A row
#define HS_STRIDE 72            // u32 words per H' pair-row (16 pair-rows/tile)
#define STAGES 3
#define A_STAGE (BM * AS_STRIDE)
#define H_STAGE (16 * HS_STRIDE)
#define SPMM_SMEM_BYTES (STAGES * (A_STAGE + H_STAGE) * 4)

__device__ __forceinline__ void spmm_load_tile(
    const float* __restrict__ A, const uint32_t* __restrict__ Hp,
    float* as, uint32_t* hs, int row0, int k0, int tid)
{
#pragma unroll
    for (int i = 0; i < 4; i++) {
        int idx = tid + i * 256;
        int r   = idx >> 3;
        int c4  = (idx & 7) << 2;
        cp16(as + r * AS_STRIDE + c4, A + (size_t)(row0 + r) * N_NODES + k0 + c4);
    }
    {
        int r  = tid >> 4;
        int c4 = (tid & 15) << 2;
        cp16(hs + r * HS_STRIDE + c4,
             Hp + (size_t)((k0 >> 1) + r) * HID + c4);
    }
}

__global__ void __launch_bounds__(256, 3) spmm_kernel(
    const float* __restrict__ adjA, int nA, const uint32_t* __restrict__ hA,
    const float* __restrict__ adjB, const uint32_t* __restrict__ hB,
    float* __restrict__ part, int kPerSplit)
{
    extern __shared__ float smem[];
    float*    AsBase = smem;
    uint32_t* HsBase = (uint32_t*)(smem + STAGES * A_STAGE);

    int b = blockIdx.y;
    const float* A;
    const uint32_t* Hp;
    if (b < nA) { A = adjA + (size_t)b * N_NODES * N_NODES;        Hp = hA; }
    else        { A = adjB + (size_t)(b - nA) * N_NODES * N_NODES; Hp = hB; }

    float* Cb = part + ((size_t)blockIdx.z * gridDim.y + b) * (size_t)(N_NODES * HID);

    int tid  = threadIdx.x;
    int lane = tid & 31;
    int warp = tid >> 5;
    int g = lane >> 2;
    int t = lane & 3;
    int wm = (warp & 3) * 32;
    int wn = (warp >> 2) * 32;
    int row0 = blockIdx.x * BM;
    int kbeg = blockIdx.z * kPerSplit;
    int nt = kPerSplit / BK;

    float acc[2][4][4];
#pragma unroll
    for (int mt = 0; mt < 2; mt++)
#pragma unroll
        for (int ntl = 0; ntl < 4; ntl++)
#pragma unroll
            for (int i = 0; i < 4; i++) acc[mt][ntl][i] = 0.f;

    // prologue: tiles 0,1 into stages 0,1
#pragma unroll
    for (int p = 0; p < STAGES - 1; p++) {
        spmm_load_tile(A, Hp, AsBase + p * A_STAGE, HsBase + p * H_STAGE,
                       row0, kbeg + p * BK, tid);
        cp_commit();
    }

    for (int j = 0; j < nt; j++) {
        cp_wait1();            // tile j resident (this thread)
        __syncthreads();       // publish tile j; retire stragglers of j-1

        // prefetch tile j+2 into stage (j+2)%3 (== stage of tile j-1, now free)
        if (j + 2 < nt) {
            int st = (j + 2) % STAGES;
            spmm_load_tile(A, Hp, AsBase + st * A_STAGE, HsBase + st * H_STAGE,
                           row0, kbeg + (j + 2) * BK, tid);
        }
        cp_commit();           // uniform group count (possibly empty)

        const float*    as = AsBase + (j % STAGES) * A_STAGE;
        const uint32_t* hs = HsBase + (j % STAGES) * H_STAGE;

#pragma unroll
        for (int c = 0; c < 2; c++) {
            int kk  = c * 16;
            int kp0 = c * 8;
            uint32_t bf[4][2];
#pragma unroll
            for (int ntl = 0; ntl < 4; ntl++) {
                int col = wn + ntl * 8 + g;
                bf[ntl][0] = hs[(kp0 + t)     * HS_STRIDE + col];
                bf[ntl][1] = hs[(kp0 + t + 4) * HS_STRIDE + col];
            }
#pragma unroll
            for (int mt = 0; mt < 2; mt++) {
                int rbase = wm + mt * 16;
                uint32_t af[4];
                af[0] = ld_scale_pack(&as[(rbase + g)     * AS_STRIDE + kk + 2 * t]);
                af[1] = ld_scale_pack(&as[(rbase + g + 8) * AS_STRIDE + kk + 2 * t]);
                af[2] = ld_scale_pack(&as[(rbase + g)     * AS_STRIDE + kk + 2 * t + 8]);
                af[3] = ld_scale_pack(&as[(rbase + g + 8) * AS_STRIDE + kk + 2 * t + 8]);
#pragma unroll
                for (int ntl = 0; ntl < 4; ntl++)
                    mma_fp16(acc[mt][ntl], af, bf[ntl]);
            }
        }
    }

#pragma unroll
    for (int mt = 0; mt < 2; mt++) {
        int r_lo = row0 + wm + mt * 16 + g;
#pragma unroll
        for (int ntl = 0; ntl < 4; ntl++) {
            int col = wn + ntl * 8 + 2 * t;
            *(float2*)&Cb[(size_t)r_lo * HID + col] =
                make_float2(acc[mt][ntl][0] * ADJ_UNSCALE,
                            acc[mt][ntl][1] * ADJ_UNSCALE);
            *(float2*)&Cb[(size_t)(r_lo + 8) * HID + col] =
                make_float2(acc[mt][ntl][2] * ADJ_UNSCALE,
                            acc[mt][ntl][3] * ADJ_UNSCALE);
        }
    }
}

// ---------------- fused split-K reduce + transform ---------------------------
__global__ void __launch_bounds__(256) relz_kernel(
    const float* __restrict__ part, int NB, int KS, int batch0,
    const float* __restrict__ W, const float* __restrict__ bias,
    float* __restrict__ Z, int wStride, int bStride)
{
    int batch = batch0 + blockIdx.y;
    const float* Wb = W + (size_t)blockIdx.y * wStride;
    const float* bb = bias + (size_t)blockIdx.y * bStride;
    float* Zb = Z + (size_t)blockIdx.y * N_NODES * HID;

    __shared__ float Ws[HID * HID];
    __shared__ float xs[16][HID];

    int tx = threadIdx.x, ty = threadIdx.y;
    int tid = ty * 64 + tx;
    for (int i = tid; i < HID * HID; i += 256)
        Ws[i] = Wb[i];

    int row0 = blockIdx.x * 16;
    const size_t slab = (size_t)N_NODES * HID;
#pragma unroll
    for (int i = 0; i < 4; i++) {
        int idx = tid + i * 256;
        int r = idx >> 6, c = idx & 63;
        float v = 0.f;
        for (int s = 0; s < KS; s++)
            v += part[(size_t)(s * NB + batch) * slab + (size_t)(row0 + r) * HID + c];
        xs[r][c] = v;
    }
    __syncthreads();

    float acc0 = bb[tx], acc1 = acc0, acc2 = acc0, acc3 = acc0;
    int rb = ty * 4;
#pragma unroll
    for (int k = 0; k < HID; k += 4) {
        float w0 = Ws[(k + 0) * HID + tx];
        float w1 = Ws[(k + 1) * HID + tx];
        float w2 = Ws[(k + 2) * HID + tx];
        float w3 = Ws[(k + 3) * HID + tx];
        float4 x0 = *(const float4*)&xs[rb + 0][k];
        float4 x1 = *(const float4*)&xs[rb + 1][k];
        float4 x2 = *(const float4*)&xs[rb + 2][k];
        float4 x3 = *(const float4*)&xs[rb + 3][k];
        acc0 = fmaf(x0.x, w0, fmaf(x0.y, w1, fmaf(x0.z, w2, fmaf(x0.w, w3, acc0))));
        acc1 = fmaf(x1.x, w0, fmaf(x1.y, w1, fmaf(x1.z, w2, fmaf(x1.w, w3, acc1))));
        acc2 = fmaf(x2.x, w0, fmaf(x2.y, w1, fmaf(x2.z, w2, fmaf(x2.w, w3, acc2))));
        acc3 = fmaf(x3.x, w0, fmaf(x3.y, w1, fmaf(x3.z, w2, fmaf(x3.w, w3, acc3))));
    }
    Zb[(size_t)(row0 + rb + 0) * HID + tx] = tanhf(acc0);
    Zb[(size_t)(row0 + rb + 1) * HID + tx] = tanhf(acc1);
    Zb[(size_t)(row0 + rb + 2) * HID + tx] = tanhf(acc2);
    Zb[(size_t)(row0 + rb + 3) * HID + tx] = tanhf(acc3);
}

// ---------------- attention pooling over K slots ----------------------------
__global__ void __launch_bounds__(128) attn_kernel(
    const float* __restrict__ Z, const float* __restrict__ aW,
    const float* __restrict__ ab, const float* __restrict__ aq,
    float* __restrict__ outp, int K)
{
    int n = blockIdx.x;
    int j = threadIdx.x;
    __shared__ float zs[4 * HID];
    __shared__ float red[ATT_H];
    __shared__ float sc[4];

    for (int k = 0; k < K; k++)
        if (j < HID) zs[k * HID + j] = Z[((size_t)k * N_NODES + n) * HID + j];
    __syncthreads();

    for (int k = 0; k < K; k++) {
        float u = ab[j];
#pragma unroll
        for (int d = 0; d < HID; d++)
            u = fmaf(zs[k * HID + d], aW[d * ATT_H + j], u);
        red[j] = tanhf(u) * aq[j];
        __syncthreads();
#pragma unroll
        for (int off = 64; off >= 1; off >>= 1) {
            if (j < off) red[j] += red[j + off];
            __syncthreads();
        }
        if (j == 0) sc[k] = red[0];
        __syncthreads();
    }

    float mx = -1e30f;
    for (int k = 0; k < K; k++) mx = fmaxf(mx, sc[k]);
    float e[4]; float den = 0.f;
    for (int k = 0; k < K; k++) { e[k] = expf(sc[k] - mx); den += e[k]; }

    if (j < HID) {
        float o = 0.f;
        for (int k = 0; k < K; k++) o += (e[k] / den) * zs[k * HID + j];
        outp[(size_t)n * HID + j] = o;
    }
}

// ---------------- final: attention over {relagg, itemitem}, then project ----
__global__ void __launch_bounds__(128) final_kernel(
    const float* __restrict__ Hrel, const float* __restrict__ Hii,
    const float* __restrict__ aW, const float* __restrict__ ab,
    const float* __restrict__ aq, const float* __restrict__ Wout,
    const float* __restrict__ bout, float* __restrict__ out, int out_total)
{
    int n = blockIdx.x;
    int j = threadIdx.x;
    __shared__ float zs[2 * HID];
    __shared__ float red[ATT_H];
    __shared__ float sc[2];
    __shared__ float pooled[HID];

    if (j < HID) {
        zs[j]       = Hrel[(size_t)n * HID + j];
        zs[HID + j] = Hii [(size_t)n * HID + j];
    }
    __syncthreads();

    for (int k = 0; k < 2; k++) {
        float u = ab[j];
#pragma unroll
        for (int d = 0; d < HID; d++)
            u = fmaf(zs[k * HID + d], aW[d * ATT_H + j], u);
        red[j] = tanhf(u) * aq[j];
        __syncthreads();
#pragma unroll
        for (int off = 64; off >= 1; off >>= 1) {
            if (j < off) red[j] += red[j + off];
            __syncthreads();
        }
        if (j == 0) sc[k] = red[0];
        __syncthreads();
    }

    float mx = fmaxf(sc[0], sc[1]);
    float e0 = expf(sc[0] - mx), e1 = expf(sc[1] - mx);
    float den = e0 + e1;
    float b0 = e0 / den, b1 = e1 / den;

    if (j < HID) pooled[j] = b0 * zs[j] + b1 * zs[HID + j];
    __syncthreads();

    if (j < OUT_DIM) {
        float o = bout[j];
#pragma unroll
        for (int d = 0; d < HID; d++)
            o = fmaf(pooled[d], Wout[d * OUT_DIM + j], o);
        out[(size_t)n * OUT_DIM + j] = o;
    }
    if (out_total > N_NODES * OUT_DIM && j < HID)
        out[(size_t)N_NODES * OUT_DIM + (size_t)n * HID + j] = pooled[j];
}

// ---------------- launch ----------------------------------------------------
extern "C" void kernel_launch(void* const* d_in, const int* in_sizes, int n_in,
                              void* d_out, int out_size)
{
    const float* feat_item = (const float*)d_in[0];
    const float* feat_user = (const float*)d_in[1];
    const float* adj_ii    = (const float*)d_in[2];
    const float* adj_mp    = (const float*)d_in[3];
    const float* adj_ui    = (const float*)d_in[4];
    const float* W_map0 = (const float*)d_in[5];
    const float* b_map0 = (const float*)d_in[6];
    const float* W_map1 = (const float*)d_in[7];
    const float* b_map1 = (const float*)d_in[8];
    const float* W_rel  = (const float*)d_in[9];
    const float* b_rel  = (const float*)d_in[10];
    const float* rel_aW = (const float*)d_in[11];
    const float* rel_ab = (const float*)d_in[12];
    const float* rel_aq = (const float*)d_in[13];
    const float* W_sch  = (const float*)d_in[14];
    const float* b_sch  = (const float*)d_in[15];
    const float* sch_aW = (const float*)d_in[16];
    const float* sch_ab = (const float*)d_in[17];
    const float* sch_aq = (const float*)d_in[18];
    const float* W_ii   = (const float*)d_in[19];
    const float* b_ii   = (const float*)d_in[20];
    const float* ii_aW  = (const float*)d_in[21];
    const float* ii_ab  = (const float*)d_in[22];
    const float* ii_aq  = (const float*)d_in[23];
    const float* fin_aW = (const float*)d_in[24];
    const float* fin_ab = (const float*)d_in[25];
    const float* fin_aq = (const float*)d_in[26];
    const float* W_out  = (const float*)d_in[27];
    const float* b_out  = (const float*)d_in[28];

    float *h0, *h1, *partb, *z3, *z2, *zii, *relagg, *itemcls, *itemitem;
    uint32_t *h0p, *h1p, *ictp;
    cudaGetSymbolAddress((void**)&h0,  g_h0);
    cudaGetSymbolAddress((void**)&h1,  g_h1);
    cudaGetSymbolAddress((void**)&h0p, g_h0p);
    cudaGetSymbolAddress((void**)&h1p, g_h1p);
    cudaGetSymbolAddress((void**)&ictp, g_ictp);
    cudaGetSymbolAddress((void**)&partb, g_part);
    cudaGetSymbolAddress((void**)&z3, g_z3);
    cudaGetSymbolAddress((void**)&z2, g_z2);
    cudaGetSymbolAddress((void**)&zii, g_zii);
    cudaGetSymbolAddress((void**)&relagg,   g_relagg);
    cudaGetSymbolAddress((void**)&itemcls,  g_itemcls);
    cudaGetSymbolAddress((void**)&itemitem, g_itemitem);

    cudaFuncSetAttribute(spmm_kernel,
                         cudaFuncAttributeMaxDynamicSharedMemorySize,
                         SPMM_SMEM_BYTES);

    dim3 blk64x4(64, 4);
    const int packBlocks = N_NODES * HID / 2 / 256;

    // Stage 1: feature mapping + fp16 pack
    map_kernel<<<N_NODES / 4, blk64x4>>>(feat_item, W_map0, b_map0, h0);
    map_kernel<<<N_NODES / 4, blk64x4>>>(feat_user, W_map1, b_map1, h1);
    pack_kernel<<<packBlocks, 256>>>(h0, h0p);
    pack_kernel<<<packBlocks, 256>>>(h1, h1p);

    // Stage 2: phase-A GEMMs (3x adj_mp@h0 + 2x adj_ui@h1), split-K=2
    // 480 CTAs on 444 slots (3 CTA/SM) = 1.08 waves
    spmm_kernel<<<dim3(N_NODES / BM, 5, 2), 256, SPMM_SMEM_BYTES>>>(
        adj_mp, 3, h0p, adj_ui, h1p, partb, N_NODES / 2);

    // Stage 3: fused reduce+transform, then attention pooling
    relz_kernel<<<dim3(N_NODES / 16, 3), blk64x4>>>(
        partb, 5, 2, 0, W_rel, b_rel, z3, HID * HID, HID);
    relz_kernel<<<dim3(N_NODES / 16, 2), blk64x4>>>(
        partb, 5, 2, 3, W_sch, b_sch, z2, 0, 0);
    attn_kernel<<<N_NODES, 128>>>(z3, rel_aW, rel_ab, rel_aq, relagg, 3);
    attn_kernel<<<N_NODES, 128>>>(z2, sch_aW, sch_ab, sch_aq, itemcls, 2);
    pack_kernel<<<packBlocks, 256>>>(itemcls, ictp);

    // Stage 4: phase-B GEMMs (2x adj_ii@itemcls), split-K=4 -> 384 CTAs, 1 wave
    spmm_kernel<<<dim3(N_NODES / BM, 2, 4), 256, SPMM_SMEM_BYTES>>>(
        adj_ii, 2, ictp, adj_ii, ictp, partb, N_NODES / 4);

    // Stage 5: fused reduce+transform + attention
    relz_kernel<<<dim3(N_NODES / 16, 2), blk64x4>>>(
        partb, 2, 4, 0, W_ii, b_ii, zii, HID * HID, HID);
    attn_kernel<<<N_NODES, 128>>>(zii, ii_aW, ii_ab, ii_aq, itemitem, 2);

    // Stage 6: final attention + projection
    final_kernel<<<N_NODES, 128>>>(relagg, itemitem, fin_aW, fin_ab, fin_aq,
                                   W_out, b_out, (float*)d_out, out_size);
}

// round 10
// speedup vs baseline: 1.1362x; 1.0588x over previous
#include <cuda_runtime.h>
#include <cuda.h>
#include <math.h>
#include <stdint.h>

#define N_NODES 6144
#define D_IN    256
#define HID     64
#define OUT_DIM 32
#define ATT_H   128

#define ADJ_SCALE   2048.0f
#define ADJ_UNSCALE 4.8828125e-4f   // 1/2048

// ---------------- scratch (device globals; no allocation allowed) ----------
__device__ float    g_h0[N_NODES * HID];
__device__ float    g_h1[N_NODES * HID];
__device__ uint32_t g_h0p[N_NODES * HID / 2];   // packed fp16 pairs [k/2][64]
__device__ uint32_t g_h1p[N_NODES * HID / 2];
__device__ uint32_t g_ictp[N_NODES * HID / 2];
__device__ float g_part[10 * N_NODES * HID];
__device__ float g_z3[3 * N_NODES * HID];
__device__ float g_z2[2 * N_NODES * HID];
__device__ float g_zii[2 * N_NODES * HID];
__device__ float g_relagg [N_NODES * HID];
__device__ float g_itemcls[N_NODES * HID];
__device__ float g_itemitem[N_NODES * HID];

// ---------------- helpers -----------------------------------------------------
__device__ __forceinline__ uint32_t smem_u32(const void* p) {
    uint32_t a;
    asm("{ .reg .u64 t; cvta.to.shared.u64 t, %1; cvt.u32.u64 %0, t; }"
        : "=r"(a) : "l"(p));
    return a;
}
__device__ __forceinline__ uint32_t pack_f16x2(float lo, float hi) {
    uint32_t r;
    asm("cvt.rn.f16x2.f32 %0, %1, %2;" : "=r"(r) : "f"(hi), "f"(lo));
    return r;
}
__device__ __forceinline__ uint32_t ld_scale_pack(const float* p) {
    float2 v = *(const float2*)p;
    return pack_f16x2(v.x * ADJ_SCALE, v.y * ADJ_SCALE);
}
__device__ __forceinline__ void mma_fp16(float* c, const uint32_t* a, const uint32_t* b) {
    asm("mma.sync.aligned.m16n8k16.row.col.f32.f16.f16.f32 "
        "{%0,%1,%2,%3}, {%4,%5,%6,%7}, {%8,%9}, {%0,%1,%2,%3};"
        : "+f"(c[0]), "+f"(c[1]), "+f"(c[2]), "+f"(c[3])
        : "r"(a[0]), "r"(a[1]), "r"(a[2]), "r"(a[3]),
          "r"(b[0]), "r"(b[1]));
}
__device__ __forceinline__ void cp16(void* dst, const void* src) {
    uint32_t d = (uint32_t)__cvta_generic_to_shared(dst);
    asm volatile("cp.async.cg.shared.global [%0], [%1], 16;" :: "r"(d), "l"(src));
}
__device__ __forceinline__ void cp_commit() {
    asm volatile("cp.async.commit_group;" ::: "memory");
}
__device__ __forceinline__ void cp_wait1() {
    asm volatile("cp.async.wait_group 1;" ::: "memory");
}
__device__ __forceinline__ void mbar_init(uint32_t addr, uint32_t cnt) {
    asm volatile("mbarrier.init.shared.b64 [%0], %1;" :: "r"(addr), "r"(cnt) : "memory");
}
__device__ __forceinline__ void mbar_expect_tx(uint32_t addr, uint32_t bytes) {
    asm volatile("mbarrier.arrive.expect_tx.shared.b64 _, [%0], %1;"
                 :: "r"(addr), "r"(bytes) : "memory");
}
__device__ __forceinline__ void mbar_wait(uint32_t addr, uint32_t parity) {
    uint32_t done;
    asm volatile(
        "{ .reg .pred p; mbarrier.try_wait.parity.acquire.cta.shared::cta.b64 p, [%1], %2;"
        " selp.b32 %0, 1, 0, p; }"
        : "=r"(done) : "r"(addr), "r"(parity) : "memory");
    if (!done) {
        asm volatile(
            "{ .reg .pred P1;\n"
            "WL_%=: mbarrier.try_wait.parity.acquire.cta.shared::cta.b64 P1, [%0], %1, 0x989680;\n"
            "@P1 bra.uni WD_%=;\n"
            "bra.uni WL_%=;\n"
            "WD_%=: }"
            :: "r"(addr), "r"(parity) : "memory");
    }
}
__device__ __forceinline__ void tma_load_a(
    const CUtensorMap* tm, uint32_t dst, int x, int y, int z, uint32_t mbar)
{
    asm volatile(
        "cp.async.bulk.tensor.3d.shared::cta.global.tile.mbarrier::complete_tx::bytes "
        "[%0], [%1, {%2, %3, %4}], [%5];"
        :: "r"(dst), "l"(tm), "r"(x), "r"(y), "r"(z), "r"(mbar)
        : "memory");
}

// ---------------- feature mapping: h = tanh(feat @ W + b) -------------------
__global__ void __launch_bounds__(256) map_kernel(
    const float* __restrict__ feat, const float* __restrict__ W,
    const float* __restrict__ b, float* __restrict__ out)
{
    int row = blockIdx.x * 4 + threadIdx.y;
    int col = threadIdx.x;
    const float* fr = feat + (size_t)row * D_IN;
    float acc = b[col];
#pragma unroll 8
    for (int k = 0; k < D_IN; k++)
        acc = fmaf(fr[k], W[k * HID + col], acc);
    out[(size_t)row * HID + col] = tanhf(acc);
}

// ---------------- pack: f32 [N][64] -> u32 half2 [N/2][64] -------------------
__global__ void __launch_bounds__(256) pack_kernel(
    const float* __restrict__ in, uint32_t* __restrict__ out)
{
    int i = blockIdx.x * 256 + threadIdx.x;
    int r = i >> 6, c = i & 63;
    float lo = in[(size_t)(2 * r) * HID + c];
    float hi = in[(size_t)(2 * r + 1) * HID + c];
    out[i] = pack_f16x2(lo, hi);
}

// ---------------- big GEMM: TMA A-tiles + cp.async H + fp16 mma --------------
// BM=128, BN=64, BK=32. 256 threads = 8 warps (4M x 2N), warp tile 32x32.
#define BM 128
#define BK 32
#define HS_STRIDE 72                 // u32 words per H' pair-row
#define STAGES 3
#define A_TILE_BYTES (BM * 128)      // 128 rows x 128B (32 f32), SW128 swizzled
#define H_STAGE_BYTES (16 * HS_STRIDE * 4)
#define A_OFF 1024
#define H_OFF (A_OFF + STAGES * A_TILE_BYTES)
#define SPMM_SMEM_BYTES (H_OFF + STAGES * H_STAGE_BYTES)

__device__ __forceinline__ void spmm_load_h(
    const uint32_t* __restrict__ Hp, uint32_t* hs, int k0, int tid)
{
    int r  = tid >> 4;
    int c4 = (tid & 15) << 2;
    cp16(hs + r * HS_STRIDE + c4, Hp + (size_t)((k0 >> 1) + r) * HID + c4);
}

__global__ void __launch_bounds__(256, 3) spmm_kernel(
    const __grid_constant__ CUtensorMap tmA,
    const __grid_constant__ CUtensorMap tmB,
    int nA, const uint32_t* __restrict__ hA, const uint32_t* __restrict__ hB,
    float* __restrict__ part, int kPerSplit)
{
    extern __shared__ __align__(1024) char smem[];
    uint32_t sbase = smem_u32(smem);

    int b = blockIdx.y;
    const CUtensorMap* tm;
    const uint32_t* Hp;
    int zc;
    if (b < nA) { tm = &tmA; zc = b;      Hp = hA; }
    else        { tm = &tmB; zc = b - nA; Hp = hB; }

    float* Cb = part + ((size_t)blockIdx.z * gridDim.y + b) * (size_t)(N_NODES * HID);
    uint32_t* HsBase = (uint32_t*)(smem + H_OFF);

    int tid  = threadIdx.x;
    int lane = tid & 31;
    int warp = tid >> 5;
    int g = lane >> 2;
    int t = lane & 3;
    int wm = (warp & 3) * 32;
    int wn = (warp >> 2) * 32;
    int row0 = blockIdx.x * BM;
    int kbeg = blockIdx.z * kPerSplit;
    int nt = kPerSplit / BK;

    if (tid == 0)
        for (int s = 0; s < STAGES; s++)
            mbar_init(sbase + s * 8, 1);
    __syncthreads();

    float acc[2][4][4];
#pragma unroll
    for (int mt = 0; mt < 2; mt++)
#pragma unroll
        for (int ntl = 0; ntl < 4; ntl++)
#pragma unroll
            for (int i = 0; i < 4; i++) acc[mt][ntl][i] = 0.f;

    // prologue: tiles 0,1
#pragma unroll
    for (int p = 0; p < STAGES - 1; p++) {
        if (tid == 0) {
            mbar_expect_tx(sbase + p * 8, A_TILE_BYTES);
            tma_load_a(tm, sbase + A_OFF + p * A_TILE_BYTES,
                       kbeg + p * BK, row0, zc, sbase + p * 8);
        }
        spmm_load_h(Hp, HsBase + p * (H_STAGE_BYTES / 4), kbeg + p * BK, tid);
        cp_commit();
    }

    for (int j = 0; j < nt; j++) {
        mbar_wait(sbase + (j % STAGES) * 8, (j / STAGES) & 1);  // A tile j done
        cp_wait1();                                             // H tile j done
        __syncthreads();   // publish; compute(j-1) fully retired by all threads

        if (j + 2 < nt) {
            int st = (j + 2) % STAGES;
            if (tid == 0) {
                mbar_expect_tx(sbase + st * 8, A_TILE_BYTES);
                tma_load_a(tm, sbase + A_OFF + st * A_TILE_BYTES,
                           kbeg + (j + 2) * BK, row0, zc, sbase + st * 8);
            }
            spmm_load_h(Hp, HsBase + st * (H_STAGE_BYTES / 4), kbeg + (j + 2) * BK, tid);
        }
        cp_commit();   // uniform group count (possibly empty)

        const char*     as = smem + A_OFF + (j % STAGES) * A_TILE_BYTES;
        const uint32_t* hs = HsBase + (j % STAGES) * (H_STAGE_BYTES / 4);

#pragma unroll
        for (int c = 0; c < 2; c++) {
            int kk  = c * 16;            // f32 col offset within 32-col tile
            int kp0 = c * 8;
            uint32_t bf[4][2];
#pragma unroll
            for (int ntl = 0; ntl < 4; ntl++) {
                int col = wn + ntl * 8 + g;
                bf[ntl][0] = hs[(kp0 + t)     * HS_STRIDE + col];
                bf[ntl][1] = hs[(kp0 + t + 4) * HS_STRIDE + col];
            }
#pragma unroll
            for (int mt = 0; mt < 2; mt++) {
                int r0l = wm + mt * 16 + g;         // local row of a0/a2
                int r1l = r0l + 8;                  // local row of a1/a3
                uint32_t m0 = (uint32_t)(r0l & 7) << 4;   // SW128 XOR mask
                uint32_t m1 = (uint32_t)(r1l & 7) << 4;
                uint32_t base0 = (uint32_t)(r0l * 128 + (kk + 2 * t) * 4);
                uint32_t base1 = (uint32_t)(r1l * 128 + (kk + 2 * t) * 4);
                uint32_t af[4];
                af[0] = ld_scale_pack((const float*)(as + (base0 ^ m0)));
                af[1] = ld_scale_pack((const float*)(as + (base1 ^ m1)));
                af[2] = ld_scale_pack((const float*)(as + ((base0 + 32) ^ m0)));
                af[3] = ld_scale_pack((const float*)(as + ((base1 + 32) ^ m1)));
#pragma unroll
                for (int ntl = 0; ntl < 4; ntl++)
                    mma_fp16(acc[mt][ntl], af, bf[ntl]);
            }
        }
    }

#pragma unroll
    for (int mt = 0; mt < 2; mt++) {
        int r_lo = row0 + wm + mt * 16 + g;
#pragma unroll
        for (int ntl = 0; ntl < 4; ntl++) {
            int col = wn + ntl * 8 + 2 * t;
            *(float2*)&Cb[(size_t)r_lo * HID + col] =
                make_float2(acc[mt][ntl][0] * ADJ_UNSCALE,
                            acc[mt][ntl][1] * ADJ_UNSCALE);
            *(float2*)&Cb[(size_t)(r_lo + 8) * HID + col] =
                make_float2(acc[mt][ntl][2] * ADJ_UNSCALE,
                            acc[mt][ntl][3] * ADJ_UNSCALE);
        }
    }
}

// ---------------- fused split-K reduce + transform ---------------------------
__global__ void __launch_bounds__(256) relz_kernel(
    const float* __restrict__ part, int NB, int KS, int batch0,
    const float* __restrict__ W, const float* __restrict__ bias,
    float* __restrict__ Z, int wStride, int bStride)
{
    int batch = batch0 + blockIdx.y;
    const float* Wb = W + (size_t)blockIdx.y * wStride;
    const float* bb = bias + (size_t)blockIdx.y * bStride;
    float* Zb = Z + (size_t)blockIdx.y * N_NODES * HID;

    __shared__ float Ws[HID * HID];
    __shared__ float xs[16][HID];

    int tx = threadIdx.x, ty = threadIdx.y;
    int tid = ty * 64 + tx;
    for (int i = tid; i < HID * HID; i += 256)
        Ws[i] = Wb[i];

    int row0 = blockIdx.x * 16;
    const size_t slab = (size_t)N_NODES * HID;
#pragma unroll
    for (int i = 0; i < 4; i++) {
        int idx = tid + i * 256;
        int r = idx >> 6, c = idx & 63;
        float v = 0.f;
        for (int s = 0; s < KS; s++)
            v += part[(size_t)(s * NB + batch) * slab + (size_t)(row0 + r) * HID + c];
        xs[r][c] = v;
    }
    __syncthreads();

    float acc0 = bb[tx], acc1 = acc0, acc2 = acc0, acc3 = acc0;
    int rb = ty * 4;
#pragma unroll
    for (int k = 0; k < HID; k += 4) {
        float w0 = Ws[(k + 0) * HID + tx];
        float w1 = Ws[(k + 1) * HID + tx];
        float w2 = Ws[(k + 2) * HID + tx];
        float w3 = Ws[(k + 3) * HID + tx];
        float4 x0 = *(const float4*)&xs[rb + 0][k];
        float4 x1 = *(const float4*)&xs[rb + 1][k];
        float4 x2 = *(const float4*)&xs[rb + 2][k];
        float4 x3 = *(const float4*)&xs[rb + 3][k];
        acc0 = fmaf(x0.x, w0, fmaf(x0.y, w1, fmaf(x0.z, w2, fmaf(x0.w, w3, acc0))));
        acc1 = fmaf(x1.x, w0, fmaf(x1.y, w1, fmaf(x1.z, w2, fmaf(x1.w, w3, acc1))));
        acc2 = fmaf(x2.x, w0, fmaf(x2.y, w1, fmaf(x2.z, w2, fmaf(x2.w, w3, acc2))));
        acc3 = fmaf(x3.x, w0, fmaf(x3.y, w1, fmaf(x3.z, w2, fmaf(x3.w, w3, acc3))));
    }
    Zb[(size_t)(row0 + rb + 0) * HID + tx] = tanhf(acc0);
    Zb[(size_t)(row0 + rb + 1) * HID + tx] = tanhf(acc1);
    Zb[(size_t)(row0 + rb + 2) * HID + tx] = tanhf(acc2);
    Zb[(size_t)(row0 + rb + 3) * HID + tx] = tanhf(acc3);
}

// ---------------- attention pooling over K slots ----------------------------
__global__ void __launch_bounds__(128) attn_kernel(
    const float* __restrict__ Z, const float* __restrict__ aW,
    const float* __restrict__ ab, const float* __restrict__ aq,
    float* __restrict__ outp, int K)
{
    int n = blockIdx.x;
    int j = threadIdx.x;
    __shared__ float zs[4 * HID];
    __shared__ float red[ATT_H];
    __shared__ float sc[4];

    for (int k = 0; k < K; k++)
        if (j < HID) zs[k * HID + j] = Z[((size_t)k * N_NODES + n) * HID + j];
    __syncthreads();

    for (int k = 0; k < K; k++) {
        float u = ab[j];
#pragma unroll
        for (int d = 0; d < HID; d++)
            u = fmaf(zs[k * HID + d], aW[d * ATT_H + j], u);
        red[j] = tanhf(u) * aq[j];
        __syncthreads();
#pragma unroll
        for (int off = 64; off >= 1; off >>= 1) {
            if (j < off) red[j] += red[j + off];
            __syncthreads();
        }
        if (j == 0) sc[k] = red[0];
        __syncthreads();
    }

    float mx = -1e30f;
    for (int k = 0; k < K; k++) mx = fmaxf(mx, sc[k]);
    float e[4]; float den = 0.f;
    for (int k = 0; k < K; k++) { e[k] = expf(sc[k] - mx); den += e[k]; }

    if (j < HID) {
        float o = 0.f;
        for (int k = 0; k < K; k++) o += (e[k] / den) * zs[k * HID + j];
        outp[(size_t)n * HID + j] = o;
    }
}

// ---------------- final: attention over {relagg, itemitem}, then project ----
__global__ void __launch_bounds__(128) final_kernel(
    const float* __restrict__ Hrel, const float* __restrict__ Hii,
    const float* __restrict__ aW, const float* __restrict__ ab,
    const float* __restrict__ aq, const float* __restrict__ Wout,
    const float* __restrict__ bout, float* __restrict__ out, int out_total)
{
    int n = blockIdx.x;
    int j = threadIdx.x;
    __shared__ float zs[2 * HID];
    __shared__ float red[ATT_H];
    __shared__ float sc[2];
    __shared__ float pooled[HID];

    if (j < HID) {
        zs[j]       = Hrel[(size_t)n * HID + j];
        zs[HID + j] = Hii [(size_t)n * HID + j];
    }
    __syncthreads();

    for (int k = 0; k < 2; k++) {
        float u = ab[j];
#pragma unroll
        for (int d = 0; d < HID; d++)
            u = fmaf(zs[k * HID + d], aW[d * ATT_H + j], u);
        red[j] = tanhf(u) * aq[j];
        __syncthreads();
#pragma unroll
        for (int off = 64; off >= 1; off >>= 1) {
            if (j < off) red[j] += red[j + off];
            __syncthreads();
        }
        if (j == 0) sc[k] = red[0];
        __syncthreads();
    }

    float mx = fmaxf(sc[0], sc[1]);
    float e0 = expf(sc[0] - mx), e1 = expf(sc[1] - mx);
    float den = e0 + e1;
    float b0 = e0 / den, b1 = e1 / den;

    if (j < HID) pooled[j] = b0 * zs[j] + b1 * zs[HID + j];
    __syncthreads();

    if (j < OUT_DIM) {
        float o = bout[j];
#pragma unroll
        for (int d = 0; d < HID; d++)
            o = fmaf(pooled[d], Wout[d * OUT_DIM + j], o);
        out[(size_t)n * OUT_DIM + j] = o;
    }
    if (out_total > N_NODES * OUT_DIM && j < HID)
        out[(size_t)N_NODES * OUT_DIM + (size_t)n * HID + j] = pooled[j];
}

// ---------------- host: tensor map creation ----------------------------------
typedef CUresult (*EncodeTiledFn)(
    CUtensorMap*, CUtensorMapDataType, cuuint32_t, void*,
    const cuuint64_t*, const cuuint64_t*, const cuuint32_t*, const cuuint32_t*,
    CUtensorMapInterleave, CUtensorMapSwizzle, CUtensorMapL2promotion,
    CUtensorMapFloatOOBfill);

static void make_adj_map(EncodeTiledFn enc, CUtensorMap* tm, const void* base, int nb)
{
    cuuint64_t dims[3]    = { N_NODES, N_NODES, (cuuint64_t)nb };
    cuuint64_t strides[2] = { (cuuint64_t)N_NODES * 4,
                              (cuuint64_t)N_NODES * N_NODES * 4 };
    cuuint32_t box[3]     = { BK, BM, 1 };
    cuuint32_t estr[3]    = { 1, 1, 1 };
    enc(tm, CU_TENSOR_MAP_DATA_TYPE_FLOAT32, 3, (void*)base,
        dims, strides, box, estr,
        CU_TENSOR_MAP_INTERLEAVE_NONE, CU_TENSOR_MAP_SWIZZLE_128B,
        CU_TENSOR_MAP_L2_PROMOTION_L2_128B, CU_TENSOR_MAP_FLOAT_OOB_FILL_NONE);
}

// ---------------- launch ----------------------------------------------------
extern "C" void kernel_launch(void* const* d_in, const int* in_sizes, int n_in,
                              void* d_out, int out_size)
{
    const float* feat_item = (const float*)d_in[0];
    const float* feat_user = (const float*)d_in[1];
    const float* adj_ii    = (const float*)d_in[2];
    const float* adj_mp    = (const float*)d_in[3];
    const float* adj_ui    = (const float*)d_in[4];
    const float* W_map0 = (const float*)d_in[5];
    const float* b_map0 = (const float*)d_in[6];
    const float* W_map1 = (const float*)d_in[7];
    const float* b_map1 = (const float*)d_in[8];
    const float* W_rel  = (const float*)d_in[9];
    const float* b_rel  = (const float*)d_in[10];
    const float* rel_aW = (const float*)d_in[11];
    const float* rel_ab = (const float*)d_in[12];
    const float* rel_aq = (const float*)d_in[13];
    const float* W_sch  = (const float*)d_in[14];
    const float* b_sch  = (const float*)d_in[15];
    const float* sch_aW = (const float*)d_in[16];
    const float* sch_ab = (const float*)d_in[17];
    const float* sch_aq = (const float*)d_in[18];
    const float* W_ii   = (const float*)d_in[19];
    const float* b_ii   = (const float*)d_in[20];
    const float* ii_aW  = (const float*)d_in[21];
    const float* ii_ab  = (const float*)d_in[22];
    const float* ii_aq  = (const float*)d_in[23];
    const float* fin_aW = (const float*)d_in[24];
    const float* fin_ab = (const float*)d_in[25];
    const float* fin_aq = (const float*)d_in[26];
    const float* W_out  = (const float*)d_in[27];
    const float* b_out  = (const float*)d_in[28];

    float *h0, *h1, *partb, *z3, *z2, *zii, *relagg, *itemcls, *itemitem;
    uint32_t *h0p, *h1p, *ictp;
    cudaGetSymbolAddress((void**)&h0,  g_h0);
    cudaGetSymbolAddress((void**)&h1,  g_h1);
    cudaGetSymbolAddress((void**)&h0p, g_h0p);
    cudaGetSymbolAddress((void**)&h1p, g_h1p);
    cudaGetSymbolAddress((void**)&ictp, g_ictp);
    cudaGetSymbolAddress((void**)&partb, g_part);
    cudaGetSymbolAddress((void**)&z3, g_z3);
    cudaGetSymbolAddress((void**)&z2, g_z2);
    cudaGetSymbolAddress((void**)&zii, g_zii);
    cudaGetSymbolAddress((void**)&relagg,   g_relagg);
    cudaGetSymbolAddress((void**)&itemcls,  g_itemcls);
    cudaGetSymbolAddress((void**)&itemitem, g_itemitem);

    // driver entry point for tensor-map encoding (no -lcuda needed)
    EncodeTiledFn enc = nullptr;
    {
        void* fp = nullptr;
        cudaDriverEntryPointQueryResult qr;
        cudaGetDriverEntryPoint("cuTensorMapEncodeTiled", &fp,
                                cudaEnableDefault, &qr);
        enc = (EncodeTiledFn)fp;
    }
    CUtensorMap tm_mp, tm_ui, tm_ii;
    make_adj_map(enc, &tm_mp, adj_mp, 3);
    make_adj_map(enc, &tm_ui, adj_ui, 2);
    make_adj_map(enc, &tm_ii, adj_ii, 2);

    cudaFuncSetAttribute(spmm_kernel,
                         cudaFuncAttributeMaxDynamicSharedMemorySize,
                         SPMM_SMEM_BYTES);

    dim3 blk64x4(64, 4);
    const int packBlocks = N_NODES * HID / 2 / 256;

    // Stage 1: feature mapping + fp16 pack
    map_kernel<<<N_NODES / 4, blk64x4>>>(feat_item, W_map0, b_map0, h0);
    map_kernel<<<N_NODES / 4, blk64x4>>>(feat_user, W_map1, b_map1, h1);
    pack_kernel<<<packBlocks, 256>>>(h0, h0p);
    pack_kernel<<<packBlocks, 256>>>(h1, h1p);

    // Stage 2: phase-A GEMMs (3x adj_mp@h0 + 2x adj_ui@h1), split-K=2
    spmm_kernel<<<dim3(N_NODES / BM, 5, 2), 256, SPMM_SMEM_BYTES>>>(
        tm_mp, tm_ui, 3, h0p, h1p, partb, N_NODES / 2);

    // Stage 3: fused reduce+transform, then attention pooling
    relz_kernel<<<dim3(N_NODES / 16, 3), blk64x4>>>(
        partb, 5, 2, 0, W_rel, b_rel, z3, HID * HID, HID);
    relz_kernel<<<dim3(N_NODES / 16, 2), blk64x4>>>(
        partb, 5, 2, 3, W_sch, b_sch, z2, 0, 0);
    attn_kernel<<<N_NODES, 128>>>(z3, rel_aW, rel_ab, rel_aq, relagg, 3);
    attn_kernel<<<N_NODES, 128>>>(z2, sch_aW, sch_ab, sch_aq, itemcls, 2);
    pack_kernel<<<packBlocks, 256>>>(itemcls, ictp);

    // Stage 4: phase-B GEMMs (2x adj_ii@itemcls), split-K=4
    spmm_kernel<<<dim3(N_NODES / BM, 2, 4), 256, SPMM_SMEM_BYTES>>>(
        tm_ii, tm_ii, 2, ictp, ictp, partb, N_NODES / 4);

    // Stage 5: fused reduce+transform + attention
    relz_kernel<<<dim3(N_NODES / 16, 2), blk64x4>>>(
        partb, 2, 4, 0, W_ii, b_ii, zii, HID * HID, HID);
    attn_kernel<<<N_NODES, 128>>>(zii, ii_aW, ii_ab, ii_aq, itemitem, 2);

    // Stage 6: final attention + projection
    final_kernel<<<N_NODES, 128>>>(relagg, itemitem, fin_aW, fin_ab, fin_aq,
                                   W_out, b_out, (float*)d_out, out_size);
}